// round 4
// baseline (speedup 1.0000x reference)
#include <cuda_runtime.h>

#define DIM     512
#define D_INNER 1024
#define DT_RANK 32
#define D_STATE 16
#define B_SZ    4
#define N_TOK   4097

// ---- kernel 1 layout: q/prefetch blocks then copy blocks ----
#define QP_BLOCKS 256
#define CP_BLOCKS 2048

// ---- kernel 2 (chain) layout ----
#define S1_BLK  128
#define S2_BASE 128
#define S2_BLK  4
#define S3_BASE 132
#define S3_BLK  64
#define S4_BASE 196
#define S4_BLK  64
#define CH_GRID 260

// ---------------- scratch + sync state (device globals) ----------------
__device__ __align__(16) float g_q    [B_SZ * DIM];
__device__ __align__(16) float g_xs   [B_SZ * D_INNER];
__device__ __align__(16) float g_sz   [B_SZ * D_INNER];
__device__ __align__(16) float g_y    [B_SZ * D_INNER];
__device__ __align__(16) float g_mixed[B_SZ * DIM];
__device__ int gc1, gc2, gc3, gc4;   // zero-init; last S4 block resets

// ---------------- helpers ----------------
__device__ __forceinline__ float siluf(float x) { return x / (1.0f + __expf(-x)); }
__device__ __forceinline__ float softplusf(float x) {
    return (x > 20.0f) ? x : log1pf(__expf(x));
}
__device__ __forceinline__ void pf_l2(const float* p) {
    asm volatile("prefetch.global.L2 [%0];" :: "l"(p));
}
__device__ __forceinline__ void wait_cnt(int* c, int target) {
    if (threadIdx.x == 0) {
        while (*(volatile int*)c < target) __nanosleep(32);
        __threadfence();
    }
    __syncthreads();
}
__device__ __forceinline__ void signal_cnt(int* c) {
    __syncthreads();
    if (threadIdx.x == 0) { __threadfence(); atomicAdd(c, 1); }
}

// Warp-collective dot of two length-(N4*4) float vectors (float4 reads).
template <int N4>
__device__ __forceinline__ float warp_dot(const float4* __restrict__ v4,
                                          const float4* __restrict__ w4) {
    int lane = threadIdx.x & 31;
    float s = 0.0f;
#pragma unroll
    for (int i = 0; i < N4 / 32; i++) {
        float4 a = v4[lane + i * 32];
        float4 b = w4[lane + i * 32];
        s += a.x * b.x + a.y * b.y + a.z * b.z + a.w * b.w;
    }
#pragma unroll
    for (int off = 16; off; off >>= 1)
        s += __shfl_xor_sync(0xffffffffu, s, off);
    return s;
}

// ============ KERNEL 1: bulk copy (streaming) + q matvec + weight prefetch ==
__global__ void __launch_bounds__(256)
k_copy_q(const float* __restrict__ x,
         const float* __restrict__ q_w,
         const float* __restrict__ in_proj_w,
         const float* __restrict__ x_proj_w,
         const float* __restrict__ dt_w,
         const float* __restrict__ out_proj_w,
         const float* __restrict__ proj_w,
         float* __restrict__ out) {
    const int t = threadIdx.x;
    const unsigned bx = blockIdx.x;

    if (bx < QP_BLOCKS) {
        // ---- one L2-prefetch line per thread across all downstream weights ----
        int tid = bx * 256 + t;                    // 0..65535
        if (tid < 32768) {                         // in_proj_w: 4MB
            pf_l2(in_proj_w + (size_t)tid * 32);
        } else if (tid < 49152) {                  // out_proj_w: 2MB
            pf_l2(out_proj_w + (size_t)(tid - 32768) * 32);
        } else if (tid < 57344) {                  // proj_w: 1MB
            pf_l2(proj_w + (size_t)(tid - 49152) * 32);
        } else if (tid < 59392) {                  // x_proj_w: 256KB
            pf_l2(x_proj_w + (size_t)(tid - 57344) * 32);
        } else if (tid < 60416) {                  // dt_w: 128KB
            pf_l2(dt_w + (size_t)(tid - 59392) * 32);
        }
        // ---- q = cls @ q_w.T : 2048 warps, 1 row each ----
        int gw = bx * 8 + (t >> 5);
        int b = gw / DIM, r = gw % DIM;
        float s = warp_dot<DIM / 4>((const float4*)(x + (size_t)b * N_TOK * DIM),
                                    (const float4*)(q_w + (size_t)r * DIM));
        if ((t & 31) == 0) g_q[b * DIM + r] = s;
        return;
    }

    // ---- streaming patch copy: evict-first so weights stay in L2 ----
    const float4* x4 = (const float4*)x;
    float4* o4 = (float4*)out;
    const int pbg = (4096 * DIM / 4) / 4;          // 131072 groups of 4 float4
    int g = (bx - QP_BLOCKS) * 256 + t;            // one group per thread
    int b   = g / pbg;
    int off = (g - b * pbg) * 4;
    int idx = b * (N_TOK * DIM / 4) + (DIM / 4) + off;   // skip cls token
    float4 v0 = __ldcs(&x4[idx]);
    float4 v1 = __ldcs(&x4[idx + 1]);
    float4 v2 = __ldcs(&x4[idx + 2]);
    float4 v3 = __ldcs(&x4[idx + 3]);
    __stcs(&o4[idx],     v0);
    __stcs(&o4[idx + 1], v1);
    __stcs(&o4[idx + 2], v2);
    __stcs(&o4[idx + 3], v3);
}

// ============ KERNEL 2: the whole chain, spin-synchronized stages ===========
__global__ void __launch_bounds__(256)
k_chain(const float* __restrict__ in_proj_w,
        const float* __restrict__ conv_w,
        const float* __restrict__ conv_b,
        const float* __restrict__ x_proj_w,
        const float* __restrict__ dt_w,
        const float* __restrict__ dt_b,
        const float* __restrict__ Dv,
        const float* __restrict__ out_proj_w,
        const float* __restrict__ proj_w,
        const float* __restrict__ proj_b,
        float* __restrict__ out) {
    const int t = threadIdx.x;
    const int lane = t & 31;
    const int wi = t >> 5;
    const unsigned bx = blockIdx.x;

    // ---- S1: xz = q @ in_proj_w.T ; conv-tap + silu (no wait; q from k1) ----
    if (bx < S1_BLK) {
        int gw = bx * 8 + wi;                      // 1024 warps, 8 outputs each
#pragma unroll
        for (int jj = 0; jj < 8; jj++) {
            int o = gw * 8 + jj;
            int b = o / (2 * D_INNER), j = o % (2 * D_INNER);
            float s = warp_dot<DIM / 4>((const float4*)(g_q + b * DIM),
                                        (const float4*)(in_proj_w + (size_t)j * DIM));
            if (lane == 0) {
                if (j < D_INNER) {
                    // causal conv at t=0: only last tap contributes
                    float v = s * conv_w[j * 4 + 3] + conv_b[j];
                    g_xs[b * D_INNER + j] = siluf(v);
                } else {
                    g_sz[b * D_INNER + (j - D_INNER)] = siluf(s);
                }
            }
        }
        signal_cnt(&gc1);
        return;
    }

    // ---- S2: x_dbl + delta + first-step scan + gate (1 block/batch) ----
    if (bx < S3_BASE) {
        __shared__ __align__(16) float s_xs[D_INNER];
        __shared__ float s_db[DT_RANK + 2 * D_STATE];   // 64
        __shared__ float s_dtv[D_INNER];
        int b = bx - S2_BASE;
        wait_cnt(&gc1, S1_BLK);

        ((float4*)s_xs)[t] = ((const float4*)(g_xs + b * D_INNER))[t];
        __syncthreads();

        // 64 rows of x_proj: 8 warps x 8 rows (coalesced, L2-warm)
#pragma unroll
        for (int rr = 0; rr < 8; rr++) {
            int r = wi * 8 + rr;
            float s = warp_dot<D_INNER / 4>((const float4*)s_xs,
                                            (const float4*)(x_proj_w + (size_t)r * D_INNER));
            if (lane == 0) s_db[r] = s;
        }
        __syncthreads();

        // delta pre-act: warp wi handles 128 rows, 2 at a time (ILP on shuffles)
        float coef = s_db[lane];   // dt coefficient k = lane (DT_RANK == 32)
        for (int rr = 0; rr < 128; rr += 2) {
            int r0 = wi * 128 + rr, r1 = r0 + 1;
            float a = dt_w[r0 * DT_RANK + lane] * coef;
            float c = dt_w[r1 * DT_RANK + lane] * coef;
#pragma unroll
            for (int off = 16; off; off >>= 1) {
                a += __shfl_xor_sync(0xffffffffu, a, off);
                c += __shfl_xor_sync(0xffffffffu, c, off);
            }
            if (lane == 0) s_dtv[r0] = a;
            if (lane == 1) s_dtv[r1] = c;
        }
        __syncthreads();

        float bc = 0.0f;
#pragma unroll
        for (int n = 0; n < D_STATE; n++)
            bc += s_db[DT_RANK + n] * s_db[DT_RANK + D_STATE + n];

#pragma unroll
        for (int p = 0; p < 4; p++) {
            int r = t + p * 256;
            float delta = softplusf(s_dtv[r] + dt_b[r]);
            float u = s_xs[r];
            // h0 = 0 => y = delta*u*(B.C) + u*D, gated by silu(z)
            g_y[b * D_INNER + r] = (delta * u * bc + u * Dv[r]) * g_sz[b * D_INNER + r];
        }
        signal_cnt(&gc2);
        return;
    }

    // ---- S3: mixed = y @ out_proj_w.T ----
    if (bx < S4_BASE) {
        int sb = bx - S3_BASE;
        wait_cnt(&gc2, S2_BLK);
        int gw = sb * 8 + wi;
#pragma unroll
        for (int j = 0; j < 4; j++) {
            int o = gw * 4 + j;
            int b = o / DIM, r = o % DIM;
            float s = warp_dot<D_INNER / 4>((const float4*)(g_y + b * D_INNER),
                                            (const float4*)(out_proj_w + (size_t)r * D_INNER));
            if (lane == 0) g_mixed[b * DIM + r] = s;
        }
        signal_cnt(&gc3);
        return;
    }

    // ---- S4: upd_cls = mixed @ proj_w.T + proj_b -> out[:,0,:] ----
    {
        int sb = bx - S4_BASE;
        wait_cnt(&gc3, S3_BLK);
        int gw = sb * 8 + wi;
#pragma unroll
        for (int j = 0; j < 4; j++) {
            int o = gw * 4 + j;
            int b = o / DIM, r = o % DIM;
            float s = warp_dot<DIM / 4>((const float4*)(g_mixed + b * DIM),
                                        (const float4*)(proj_w + (size_t)r * DIM));
            if (lane == 0)
                out[(size_t)b * N_TOK * DIM + r] = s + proj_b[r];
        }
        __syncthreads();
        if (t == 0) {
            __threadfence();
            int done = atomicAdd(&gc4, 1);
            if (done == S4_BLK - 1) {   // last block: reset for next replay
                gc1 = 0; gc2 = 0; gc3 = 0; gc4 = 0;
            }
        }
        return;
    }
}

// ---------------- launch ----------------
extern "C" void kernel_launch(void* const* d_in, const int* in_sizes, int n_in,
                              void* d_out, int out_size) {
    const float* x         = (const float*)d_in[0];
    const float* q_w       = (const float*)d_in[1];
    const float* in_proj_w = (const float*)d_in[2];
    const float* conv_w    = (const float*)d_in[3];
    const float* conv_b    = (const float*)d_in[4];
    const float* x_proj_w  = (const float*)d_in[5];
    const float* dt_w      = (const float*)d_in[6];
    const float* dt_b      = (const float*)d_in[7];
    // d_in[8] = A_log (unused: h0 = 0 at the single contributing scan step)
    const float* Dv        = (const float*)d_in[9];
    const float* out_proj_w= (const float*)d_in[10];
    const float* proj_w    = (const float*)d_in[11];
    const float* proj_b    = (const float*)d_in[12];
    float* out = (float*)d_out;

    k_copy_q<<<QP_BLOCKS + CP_BLOCKS, 256>>>(x, q_w, in_proj_w, x_proj_w,
                                             dt_w, out_proj_w, proj_w, out);
    k_chain<<<CH_GRID, 256>>>(in_proj_w, conv_w, conv_b, x_proj_w, dt_w, dt_b,
                              Dv, out_proj_w, proj_w, proj_b, out);
}

// round 7
// speedup vs baseline: 2.0899x; 2.0899x over previous
#include <cuda_runtime.h>

#define DIM     512
#define D_INNER 1024
#define DT_RANK 32
#define D_STATE 16
#define B_SZ    4
#define N_TOK   4097

// ---------------- scratch (device globals, allocation-free) ----------------
__device__ __align__(16) float g_q    [B_SZ * DIM];
__device__ __align__(16) float g_xs   [B_SZ * D_INNER];
__device__ __align__(16) float g_sz   [B_SZ * D_INNER];
__device__ __align__(16) float g_y    [B_SZ * D_INNER];
__device__ __align__(16) float g_mixed[B_SZ * DIM];

// ---------------- helpers ----------------
__device__ __forceinline__ float siluf(float x) { return x / (1.0f + __expf(-x)); }
__device__ __forceinline__ float softplusf(float x) {
    return (x > 20.0f) ? x : log1pf(__expf(x));
}
__device__ __forceinline__ void pf_l2(const float* p) {
    asm volatile("prefetch.global.L2 [%0];" :: "l"(p));
}

// Warp-collective dot of two length-(N4*4) float vectors (float4 reads).
template <int N4>
__device__ __forceinline__ float warp_dot(const float4* __restrict__ v4,
                                          const float4* __restrict__ w4) {
    int lane = threadIdx.x & 31;
    float s = 0.0f;
#pragma unroll
    for (int i = 0; i < N4 / 32; i++) {
        float4 a = v4[lane + i * 32];
        float4 b = w4[lane + i * 32];
        s += a.x * b.x + a.y * b.y + a.z * b.z + a.w * b.w;
    }
#pragma unroll
    for (int off = 16; off; off >>= 1)
        s += __shfl_xor_sync(0xffffffffu, s, off);
    return s;
}

// ============ K0: bulk patch copy (streaming; runs parallel to chain) =======
// 2048 blocks x 256 thr; each thread copies 4 float4.
__global__ void __launch_bounds__(256) k_copy(const float4* __restrict__ x4,
                                              float4* __restrict__ o4) {
    const int pbg = 4096 * DIM / 4;              // 524288 float4 per batch
    int tid = blockIdx.x * 256 + threadIdx.x;    // 0..524287
#pragma unroll
    for (int k = 0; k < 4; k++) {
        int i = tid + k * 524288;
        int b = i / pbg;
        int off = i - b * pbg;
        int idx = b * (N_TOK * DIM / 4) + (DIM / 4) + off;   // skip cls token
        __stcs(&o4[idx], __ldcs(&x4[idx]));
    }
}

// ============ K1: q = cls @ q_w.T (+ prefetch in_proj_w for K2) =============
// 256 blocks x 8 warps x 1 output = 2048 outputs.
__global__ void __launch_bounds__(256) k_q(const float* __restrict__ x,
                                           const float* __restrict__ q_w,
                                           const float* __restrict__ in_proj_w) {
    int t = threadIdx.x, wi = t >> 5, lane = t & 31;
    int tid = blockIdx.x * 256 + t;              // 0..65535
    if (tid < 32768) pf_l2(in_proj_w + (size_t)tid * 32);    // 4MB -> L2
    int o = blockIdx.x * 8 + wi;                 // 0..2047
    int b = o / DIM, r = o % DIM;
    float s = warp_dot<DIM / 4>((const float4*)(x + (size_t)b * N_TOK * DIM),
                                (const float4*)(q_w + (size_t)r * DIM));
    if (lane == 0) g_q[b * DIM + r] = s;
}

// ============ K2: xz = q @ in_proj_w.T ; conv-tap + silu ====================
// 1024 blocks x 8 warps x 1 output = 8192 outputs.
__global__ void __launch_bounds__(256) k_xz(const float* __restrict__ in_proj_w,
                                            const float* __restrict__ conv_w,
                                            const float* __restrict__ conv_b,
                                            const float* __restrict__ x_proj_w,
                                            const float* __restrict__ dt_w,
                                            const float* __restrict__ out_proj_w) {
    int t = threadIdx.x, wi = t >> 5, lane = t & 31;
    int tid = blockIdx.x * 256 + t;              // 0..262143
    // prefetch what K3/K4 need next: out_proj (16384 lines), x_proj (2048), dt_w (1024)
    if (tid < 16384)       pf_l2(out_proj_w + (size_t)tid * 32);
    else if (tid < 18432)  pf_l2(x_proj_w + (size_t)(tid - 16384) * 32);
    else if (tid < 19456)  pf_l2(dt_w + (size_t)(tid - 18432) * 32);

    int o = blockIdx.x * 8 + wi;                 // 0..8191
    int b = o / (2 * D_INNER), j = o % (2 * D_INNER);
    float s = warp_dot<DIM / 4>((const float4*)(g_q + b * DIM),
                                (const float4*)(in_proj_w + (size_t)j * DIM));
    if (lane == 0) {
        if (j < D_INNER) {
            // causal conv at t=0: only last tap contributes
            float v = s * conv_w[j * 4 + 3] + conv_b[j];
            g_xs[b * D_INNER + j] = siluf(v);
        } else {
            g_sz[b * D_INNER + (j - D_INNER)] = siluf(s);
        }
    }
}

// ============ K3: x_dbl + delta + first-step scan + gate (1 block/batch) ====
__global__ void __launch_bounds__(1024) k_scan(const float* __restrict__ x_proj_w,
                                               const float* __restrict__ dt_w,
                                               const float* __restrict__ dt_b,
                                               const float* __restrict__ Dv,
                                               const float* __restrict__ proj_w) {
    __shared__ __align__(16) float s_xs[D_INNER];
    __shared__ float s_db[DT_RANK + 2 * D_STATE];    // 64
    int b = blockIdx.x, t = threadIdx.x;
    int lane = t & 31, w = t >> 5;
    // prefetch proj_w (8192 lines) for K5 while we compute
    int gid = blockIdx.x * 1024 + t;             // 0..4095
    pf_l2(proj_w + (size_t)(2 * gid) * 32);
    pf_l2(proj_w + (size_t)(2 * gid + 1) * 32);

    s_xs[t] = g_xs[b * D_INNER + t];
    __syncthreads();

    // 64 rows of x_proj: 32 warps x 2 rows (coalesced float4 reads)
#pragma unroll
    for (int rr = 0; rr < 2; rr++) {
        int r = w * 2 + rr;
        float s = warp_dot<D_INNER / 4>((const float4*)s_xs,
                                        (const float4*)(x_proj_w + (size_t)r * D_INNER));
        if (lane == 0) s_db[r] = s;
    }
    __syncthreads();

    // delta pre-act: warp w handles rows [w*32, w*32+32), coalesced row loads
    float coef = s_db[lane];   // dt coefficient k = lane (DT_RANK == 32)
    float dtv = 0.0f;
#pragma unroll
    for (int rr = 0; rr < 32; rr++) {
        int r = w * 32 + rr;
        float v = dt_w[r * DT_RANK + lane] * coef;
#pragma unroll
        for (int off = 16; off; off >>= 1)
            v += __shfl_xor_sync(0xffffffffu, v, off);
        if (lane == rr) dtv = v;   // thread t = w*32+rr owns row t
    }
    float delta = softplusf(dtv + dt_b[t]);

    float bc = 0.0f;
#pragma unroll
    for (int n = 0; n < D_STATE; n++)
        bc += s_db[DT_RANK + n] * s_db[DT_RANK + D_STATE + n];

    float u = s_xs[t];
    // h0 = 0 => y = delta*u*(B.C) + u*D, gated by silu(z)
    g_y[b * D_INNER + t] = (delta * u * bc + u * Dv[t]) * g_sz[b * D_INNER + t];
}

// ============ K4: mixed = y @ out_proj_w.T ==================================
// 256 blocks x 8 warps x 1 output = 2048 outputs.
__global__ void __launch_bounds__(256) k_mixed(const float* __restrict__ out_proj_w) {
    int t = threadIdx.x, wi = t >> 5, lane = t & 31;
    int o = blockIdx.x * 8 + wi;
    int b = o / DIM, r = o % DIM;
    float s = warp_dot<D_INNER / 4>((const float4*)(g_y + b * D_INNER),
                                    (const float4*)(out_proj_w + (size_t)r * D_INNER));
    if (lane == 0) g_mixed[b * DIM + r] = s;
}

// ============ K5: upd_cls = mixed @ proj_w.T + proj_b -> out[:,0,:] =========
// 256 blocks x 8 warps x 1 output = 2048 outputs.
__global__ void __launch_bounds__(256) k_out(const float* __restrict__ proj_w,
                                             const float* __restrict__ proj_b,
                                             float* __restrict__ out) {
    int t = threadIdx.x, wi = t >> 5, lane = t & 31;
    int o = blockIdx.x * 8 + wi;
    int b = o / DIM, r = o % DIM;
    float s = warp_dot<DIM / 4>((const float4*)(g_mixed + b * DIM),
                                (const float4*)(proj_w + (size_t)r * DIM));
    if (lane == 0)
        out[(size_t)b * N_TOK * DIM + r] = s + proj_b[r];
}

// ---------------- launch: graph fork/join (copy ∥ chain) -------------------
extern "C" void kernel_launch(void* const* d_in, const int* in_sizes, int n_in,
                              void* d_out, int out_size) {
    const float* x         = (const float*)d_in[0];
    const float* q_w       = (const float*)d_in[1];
    const float* in_proj_w = (const float*)d_in[2];
    const float* conv_w    = (const float*)d_in[3];
    const float* conv_b    = (const float*)d_in[4];
    const float* x_proj_w  = (const float*)d_in[5];
    const float* dt_w      = (const float*)d_in[6];
    const float* dt_b      = (const float*)d_in[7];
    // d_in[8] = A_log (unused: h0 = 0 at the single contributing scan step)
    const float* Dv        = (const float*)d_in[9];
    const float* out_proj_w= (const float*)d_in[10];
    const float* proj_w    = (const float*)d_in[11];
    const float* proj_b    = (const float*)d_in[12];
    float* out = (float*)d_out;

    // One-time creation of a side stream + fork/join events (host resources
    // only — no device memory). Work performed per call is identical.
    static cudaStream_t s1 = nullptr;
    static cudaEvent_t  e0 = nullptr, e1 = nullptr;
    static bool tried = false;
    if (!tried) {
        tried = true;
        if (cudaStreamCreateWithFlags(&s1, cudaStreamNonBlocking) != cudaSuccess)
            s1 = nullptr;
        if (s1 && (cudaEventCreateWithFlags(&e0, cudaEventDisableTiming) != cudaSuccess ||
                   cudaEventCreateWithFlags(&e1, cudaEventDisableTiming) != cudaSuccess)) {
            s1 = nullptr; e0 = nullptr; e1 = nullptr;
        }
        cudaGetLastError();
    }

    if (s1 && e0 && e1) {
        // fork: chain branch on s1 runs parallel to copy on the main stream
        cudaEventRecord(e0, 0);
        cudaStreamWaitEvent(s1, e0, 0);

        k_copy <<<2048, 256, 0, 0>>>((const float4*)x, (float4*)out);

        k_q    <<<256,  256, 0, s1>>>(x, q_w, in_proj_w);
        k_xz   <<<1024, 256, 0, s1>>>(in_proj_w, conv_w, conv_b,
                                      x_proj_w, dt_w, out_proj_w);
        k_scan <<<B_SZ, 1024, 0, s1>>>(x_proj_w, dt_w, dt_b, Dv, proj_w);
        k_mixed<<<256,  256, 0, s1>>>(out_proj_w);
        k_out  <<<256,  256, 0, s1>>>(proj_w, proj_b, out);

        // join back into the main stream
        cudaEventRecord(e1, s1);
        cudaStreamWaitEvent(0, e1, 0);
    } else {
        // serial fallback (identical math; ~R2 performance)
        k_copy <<<2048, 256>>>((const float4*)x, (float4*)out);
        k_q    <<<256,  256>>>(x, q_w, in_proj_w);
        k_xz   <<<1024, 256>>>(in_proj_w, conv_w, conv_b,
                               x_proj_w, dt_w, out_proj_w);
        k_scan <<<B_SZ, 1024>>>(x_proj_w, dt_w, dt_b, Dv, proj_w);
        k_mixed<<<256,  256>>>(out_proj_w);
        k_out  <<<256,  256>>>(proj_w, proj_b, out);
    }
}